// round 3
// baseline (speedup 1.0000x reference)
#include <cuda_runtime.h>
#include <math.h>

#define NCLS 19
#define BB   8
#define CC   512
#define HW   16384      // 128*128
#define GPB  4          // channels per block
#define THREADS_A 256

// Scratch (single-writer per slot -> deterministic, no atomics on floats)
__device__ float g_partial[2][BB][NCLS][CC];   // [tensor][b][class][channel]
__device__ int   g_cnt_part[BB][NCLS];
__device__ float g_norm[2][NCLS][CC];          // normalized class means

// ---------------------------------------------------------------------------
// Kernel A: streaming segment-sum.
// Block (cg, b): channels [cg*4, cg*4+4) of image b, both tensors.
// Warp w: tensor = w&1, local channel = w>>1. Private accumulator slab
// acc[w][19][32]: bank == lane -> conflict-free, no cross-thread sharing.
// ---------------------------------------------------------------------------
__global__ void __launch_bounds__(THREADS_A) kA(const float* __restrict__ fs,
                                                const float* __restrict__ ft,
                                                const int*   __restrict__ lab) {
    extern __shared__ unsigned char smem[];
    float*         acc   = (float*)smem;                   // 8*19*32 floats = 77824 B
    unsigned char* labu8 = smem + 8 * NCLS * 32 * 4;       // 16384 B
    int*           cnt   = (int*)(labu8 + HW);             // 32 ints

    const int tid  = threadIdx.x;
    const int lane = tid & 31;
    const int w    = tid >> 5;
    const int cg   = blockIdx.x;
    const int b    = blockIdx.y;

    // zero accumulators
    for (int i = tid; i < 8 * NCLS * 32; i += THREADS_A) acc[i] = 0.0f;
    if (tid < 32) cnt[tid] = 0;

    // labels -> shared u8 (values 0..18 fit in a byte)
    const int4* lab4 = (const int4*)(lab + (size_t)b * HW);
    uchar4*     lu4  = (uchar4*)labu8;
    for (int i = tid; i < HW / 4; i += THREADS_A) {
        int4 v = lab4[i];
        lu4[i] = make_uchar4((unsigned char)v.x, (unsigned char)v.y,
                             (unsigned char)v.z, (unsigned char)v.w);
    }
    __syncthreads();

    const int tensor = w & 1;
    const int cl     = w >> 1;                 // 0..3
    const int c      = cg * GPB + cl;
    const float4* f  = (const float4*)((tensor ? ft : fs) + ((size_t)b * CC + c) * HW);
    float* accw      = acc + w * NCLS * 32;
    const unsigned int* labw = (const unsigned int*)labu8;  // 4 packed labels / word

    #pragma unroll 4
    for (int i = lane; i < HW / 4; i += 32) {
        unsigned int l = labw[i];
        float4 v = f[i];
        accw[((l      ) & 0xFFu) * 32 + lane] += v.x;
        accw[((l >>  8) & 0xFFu) * 32 + lane] += v.y;
        accw[((l >> 16) & 0xFFu) * 32 + lane] += v.z;
        accw[((l >> 24)        ) * 32 + lane] += v.w;
    }

    // per-class pixel counts: only one block per image needs to do this
    if (cg == 0) {
        for (int i = tid; i < HW; i += THREADS_A)
            atomicAdd(&cnt[labu8[i]], 1);      // shared int atomics: deterministic
    }
    __syncthreads();

    // flush: each warp reduces its own [19][32] slab
    for (int k = 0; k < NCLS; k++) {
        float v = accw[k * 32 + lane];
        #pragma unroll
        for (int o = 16; o; o >>= 1) v += __shfl_down_sync(0xFFFFFFFFu, v, o);
        if (lane == 0) g_partial[tensor][b][k][c] = v;
    }
    if (cg == 0 && tid < NCLS) g_cnt_part[b][tid] = cnt[tid];
}

// ---------------------------------------------------------------------------
// Kernel C1: per-class mean + L2 normalize. Block k, thread t = channel.
// ---------------------------------------------------------------------------
__global__ void __launch_bounds__(512) kC1() {
    __shared__ float red[512];
    __shared__ float sh_denom;
    const int k = blockIdx.x;
    const int t = threadIdx.x;

    if (t == 0) {
        int cntk = 0;
        for (int b = 0; b < BB; b++) cntk += g_cnt_part[b][k];
        sh_denom = fmaxf((float)cntk, 1.0f);
    }
    __syncthreads();
    const float denom = sh_denom;

    for (int s = 0; s < 2; s++) {
        float sum = 0.0f;
        #pragma unroll
        for (int b = 0; b < BB; b++) sum += g_partial[s][b][k][t];
        float mean = sum / denom;

        red[t] = mean * mean;
        __syncthreads();
        for (int o = 256; o; o >>= 1) {
            if (t < o) red[t] += red[t + o];
            __syncthreads();
        }
        float nrm = sqrtf(red[0]);
        __syncthreads();   // everyone read red[0] before next overwrite

        g_norm[s][k][t] = mean / fmaxf(nrm, 1e-12f);
    }
}

// ---------------------------------------------------------------------------
// Kernel C2: logits (19x19 warp-dots), logsumexp, masked mean -> scalar loss.
// ---------------------------------------------------------------------------
__global__ void __launch_bounds__(640) kC2(float* __restrict__ out) {
    __shared__ float sh_log[NCLS][NCLS];
    __shared__ int   sh_cnt[NCLS];
    __shared__ float sh_pc[NCLS];
    const int tid  = threadIdx.x;
    const int w    = tid >> 5;
    const int lane = tid & 31;

    if (tid < NCLS) {
        int c = 0;
        for (int b = 0; b < BB; b++) c += g_cnt_part[b][tid];
        sh_cnt[tid] = c;
    }

    if (w < NCLS) {                       // warp w -> logits row w
        const float* si = &g_norm[0][w][0];
        for (int j = 0; j < NCLS; j++) {
            const float* tj = &g_norm[1][j][0];
            float p = 0.0f;
            for (int c2 = lane; c2 < CC; c2 += 32) p += si[c2] * tj[c2];
            #pragma unroll
            for (int o = 16; o; o >>= 1) p += __shfl_down_sync(0xFFFFFFFFu, p, o);
            if (lane == 0) sh_log[w][j] = p * 10.0f;   // / TEMP (0.1)
        }
    }
    __syncthreads();

    if (tid < NCLS) {
        float m = -1e30f;
        for (int j = 0; j < NCLS; j++) m = fmaxf(m, sh_log[tid][j]);
        float s = 0.0f;
        for (int j = 0; j < NCLS; j++) s += expf(sh_log[tid][j] - m);
        float lse = m + logf(s);
        sh_pc[tid] = sh_log[tid][tid] - lse;
    }
    __syncthreads();

    if (tid == 0) {
        float sum = 0.0f;
        int np = 0;
        for (int k = 0; k < NCLS; k++)
            if (sh_cnt[k] > 0) { sum += sh_pc[k]; np++; }
        out[0] = -sum / (float)np;
    }
}

// ---------------------------------------------------------------------------
extern "C" void kernel_launch(void* const* d_in, const int* in_sizes, int n_in,
                              void* d_out, int out_size) {
    const float* fs  = (const float*)d_in[0];
    const float* ft  = (const float*)d_in[1];
    const int*   lab = (const int*)d_in[2];

    const size_t smemA = (size_t)8 * NCLS * 32 * 4 + HW + 32 * 4;  // 94336 B
    cudaFuncSetAttribute(kA, cudaFuncAttributeMaxDynamicSharedMemorySize, (int)smemA);

    kA<<<dim3(CC / GPB, BB), THREADS_A, smemA>>>(fs, ft, lab);
    kC1<<<NCLS, 512>>>();
    kC2<<<1, 640>>>((float*)d_out);
}

// round 4
// speedup vs baseline: 1.3645x; 1.3645x over previous
#include <cuda_runtime.h>
#include <math.h>

#define NCLS 19
#define BB   8
#define CC   512
#define HW   16384      // 128*128
#define GPB  8          // channels per block
#define THREADS_A 512   // 16 warps: tensor = w&1, local channel = w>>1

// Scratch (single-writer per slot -> deterministic, no float atomics)
__device__ float g_partial[2][BB][NCLS][CC];   // [tensor][b][class][channel]
__device__ int   g_cnt_part[BB][NCLS];
__device__ float g_norm[2][NCLS][CC];          // normalized class means

// ---------------------------------------------------------------------------
// Kernel A: streaming segment-sum.
// Block (cg, b): channels [cg*8, cg*8+8) of image b, both tensors.
// Warp w: tensor = w&1, local channel = w>>1. Private accumulator slab
// acc[w][19][32]: bank == lane -> conflict-free, no cross-thread sharing.
// smem/block = 16*2432 + 16384 + 128 = 55424 B -> 4 blocks/SM = 64 warps.
// ---------------------------------------------------------------------------
__global__ void __launch_bounds__(THREADS_A, 4) kA(const float* __restrict__ fs,
                                                   const float* __restrict__ ft,
                                                   const int*   __restrict__ lab) {
    extern __shared__ unsigned char smem[];
    float*         acc   = (float*)smem;                      // 16*19*32 floats
    unsigned char* labu8 = smem + 16 * NCLS * 32 * 4;         // 16384 B
    int*           cnt   = (int*)(labu8 + HW);                // 32 ints

    const int tid  = threadIdx.x;
    const int lane = tid & 31;
    const int w    = tid >> 5;
    const int cg   = blockIdx.x;
    const int b    = blockIdx.y;

    // zero accumulators
    for (int i = tid; i < 16 * NCLS * 32; i += THREADS_A) acc[i] = 0.0f;
    if (tid < 32) cnt[tid] = 0;

    // labels -> shared u8 (values 0..18 fit in a byte)
    const int4* lab4 = (const int4*)(lab + (size_t)b * HW);
    uchar4*     lu4  = (uchar4*)labu8;
    for (int i = tid; i < HW / 4; i += THREADS_A) {
        int4 v = lab4[i];
        lu4[i] = make_uchar4((unsigned char)v.x, (unsigned char)v.y,
                             (unsigned char)v.z, (unsigned char)v.w);
    }
    __syncthreads();

    const int tensor = w & 1;
    const int cl     = w >> 1;                 // 0..7
    const int c      = cg * GPB + cl;
    const float4* f  = (const float4*)((tensor ? ft : fs) + ((size_t)b * CC + c) * HW);
    float* accw      = acc + w * NCLS * 32;
    const unsigned int* labw = (const unsigned int*)labu8;  // 4 packed labels / word

    #pragma unroll 4
    for (int i = lane; i < HW / 4; i += 32) {
        unsigned int l = labw[i];
        float4 v = f[i];
        accw[((l      ) & 0xFFu) * 32 + lane] += v.x;
        accw[((l >>  8) & 0xFFu) * 32 + lane] += v.y;
        accw[((l >> 16) & 0xFFu) * 32 + lane] += v.z;
        accw[((l >> 24)        ) * 32 + lane] += v.w;
    }

    // per-class pixel counts: only one block per image
    if (cg == 0) {
        for (int i = tid; i < HW; i += THREADS_A)
            atomicAdd(&cnt[labu8[i]], 1);      // shared int atomics: deterministic
    }
    __syncthreads();

    // flush: each warp reduces its own [19][32] slab
    for (int k = 0; k < NCLS; k++) {
        float v = accw[k * 32 + lane];
        #pragma unroll
        for (int o = 16; o; o >>= 1) v += __shfl_down_sync(0xFFFFFFFFu, v, o);
        if (lane == 0) g_partial[tensor][b][k][c] = v;
    }
    if (cg == 0 && tid < NCLS) g_cnt_part[b][tid] = cnt[tid];
}

// ---------------------------------------------------------------------------
// Kernel C (fused): mean+normalize (warp-parallel), logits, loss.
// 640 threads = 20 warps. 38 (tensor,class) normalize tasks over warps,
// register-resident means, shuffle all-reduce -> no block tree reductions.
// ---------------------------------------------------------------------------
__global__ void __launch_bounds__(640) kC(float* __restrict__ out) {
    __shared__ float sh_log[NCLS][NCLS];
    __shared__ int   sh_cnt[NCLS];
    __shared__ float sh_pc[NCLS];
    const int tid  = threadIdx.x;
    const int w    = tid >> 5;
    const int lane = tid & 31;

    if (tid < NCLS) {
        int c = 0;
        #pragma unroll
        for (int b = 0; b < BB; b++) c += g_cnt_part[b][tid];
        sh_cnt[tid] = c;
    }
    __syncthreads();

    // normalize: task t -> tensor s = t/19, class k = t%19
    for (int t = w; t < 2 * NCLS; t += 20) {
        const int s = (t >= NCLS) ? 1 : 0;
        const int k = (t >= NCLS) ? (t - NCLS) : t;
        const float denom = fmaxf((float)sh_cnt[k], 1.0f);

        float m[CC / 32];
        float ss = 0.0f;
        #pragma unroll
        for (int ch = 0; ch < CC / 32; ch++) {
            const int c = ch * 32 + lane;
            float sum = 0.0f;
            #pragma unroll
            for (int b = 0; b < BB; b++) sum += g_partial[s][b][k][c];
            float mean = sum / denom;
            m[ch] = mean;
            ss += mean * mean;
        }
        #pragma unroll
        for (int o = 16; o; o >>= 1) ss += __shfl_xor_sync(0xFFFFFFFFu, ss, o);
        const float inv = 1.0f / fmaxf(sqrtf(ss), 1e-12f);
        #pragma unroll
        for (int ch = 0; ch < CC / 32; ch++)
            g_norm[s][k][ch * 32 + lane] = m[ch] * inv;
    }
    __syncthreads();

    if (w < NCLS) {                       // warp w -> logits row w
        const float* si = &g_norm[0][w][0];
        for (int j = 0; j < NCLS; j++) {
            const float* tj = &g_norm[1][j][0];
            float p = 0.0f;
            #pragma unroll
            for (int ch = 0; ch < CC / 32; ch++)
                p += si[ch * 32 + lane] * tj[ch * 32 + lane];
            #pragma unroll
            for (int o = 16; o; o >>= 1) p += __shfl_down_sync(0xFFFFFFFFu, p, o);
            if (lane == 0) sh_log[w][j] = p * 10.0f;   // / TEMP (0.1)
        }
    }
    __syncthreads();

    if (tid < NCLS) {
        float mx = -1e30f;
        for (int j = 0; j < NCLS; j++) mx = fmaxf(mx, sh_log[tid][j]);
        float s = 0.0f;
        for (int j = 0; j < NCLS; j++) s += expf(sh_log[tid][j] - mx);
        float lse = mx + logf(s);
        sh_pc[tid] = sh_log[tid][tid] - lse;
    }
    __syncthreads();

    if (tid == 0) {
        float sum = 0.0f;
        int np = 0;
        for (int k = 0; k < NCLS; k++)
            if (sh_cnt[k] > 0) { sum += sh_pc[k]; np++; }
        out[0] = -sum / (float)np;
    }
}

// ---------------------------------------------------------------------------
extern "C" void kernel_launch(void* const* d_in, const int* in_sizes, int n_in,
                              void* d_out, int out_size) {
    const float* fs  = (const float*)d_in[0];
    const float* ft  = (const float*)d_in[1];
    const int*   lab = (const int*)d_in[2];

    const size_t smemA = (size_t)16 * NCLS * 32 * 4 + HW + 32 * 4;  // 55424 B
    cudaFuncSetAttribute(kA, cudaFuncAttributeMaxDynamicSharedMemorySize, (int)smemA);

    kA<<<dim3(CC / GPB, BB), THREADS_A, smemA>>>(fs, ft, lab);
    kC<<<1, 640>>>((float*)d_out);
}